// round 4
// baseline (speedup 1.0000x reference)
#include <cuda_runtime.h>
#include <math.h>

// Problem constants (fixed shapes)
#define B_    16
#define H_    16
#define BH    256          // B*H
#define L_    4
#define D_    2048
#define HD_   128
#define KV_   4096
#define KVT   4100         // KV + L
#define M_    64           // B*L rows
#define CH    513          // kv chunk size
#define NCH   8            // 8*513 = 4104 >= 4100

// Output layout (concatenated): out[131072], keys[256*4100*128], values[...]
#define OUT_ELEMS   (M_*D_)                 // 131072
#define KEYS_ELEMS  (BH*KVT*HD_)            // 134348800

// Scratch
__device__ float g_qkv[3*M_*D_];            // raw q,k,v projections
__device__ float g_q[BH*L_*HD_];            // roped q, (b,h,l,hd)
__device__ float g_attnout[BH*L_*HD_];      // attention output accum (b,h,l,hd)
__device__ float g_scores[BH*L_*KVT];       // scores/probs
__device__ float g_rc[L_][64];
__device__ float g_rs[L_][64];

// ---------------------------------------------------------------------------
// init: zero accumulators + out region, build rope table (fp64 trig)
// ---------------------------------------------------------------------------
__global__ void init_kernel(float* __restrict__ out) {
    int t = blockIdx.x * blockDim.x + threadIdx.x;
    if (t < 3*M_*D_) g_qkv[t] = 0.f;
    if (t < BH*L_*HD_) { g_attnout[t] = 0.f; out[t] = 0.f; }
    if (t < 256) {
        int l = t >> 6, i = t & 63;
        double inv = pow(10000.0, -(double)(2*i) / 128.0);
        float invf = (float)inv;                       // match jax f32 inv_freq
        float ang = (float)(KV_ + l) * invf;           // f32 angle like reference
        g_rc[l][i] = (float)cos((double)ang);
        g_rs[l][i] = (float)sin((double)ang);
    }
}

// ---------------------------------------------------------------------------
// gemm64: C[64 x 2048] (+)= A[64 x 2048] * W[2048 x 2048]^T  (dot of rows)
// mode 0/1/2: A = x, C = g_qkv + mode*M*D     (split-K via gridDim.y, atomic)
// mode 3    : A = g_attnout (gathered (b,h,l,hd) -> (m,k)), C = Cext (out)
// ---------------------------------------------------------------------------
__global__ void gemm64(const float* __restrict__ A_in, const float* __restrict__ W,
                       float* __restrict__ Cext, int mode) {
    __shared__ float As[32][64];
    __shared__ float Bs[32][64];
    const bool gather = (mode == 3);
    const float* __restrict__ A = gather ? g_attnout : A_in;
    float* __restrict__ C = gather ? Cext : (g_qkv + mode * M_ * D_);

    int tid = threadIdx.x;
    int tx = tid & 15, ty = tid >> 4;
    int n0 = blockIdx.x * 64;
    int KS = D_ / gridDim.y;
    int kbase = blockIdx.y * KS;

    float acc[4][4] = {};

    for (int k0 = kbase; k0 < kbase + KS; k0 += 32) {
        #pragma unroll
        for (int rep = 0; rep < 2; rep++) {
            int fid = tid + rep * 256;
            int row = fid >> 3;
            int c4  = (fid & 7) * 4;
            int k   = k0 + c4;
            float4 av;
            if (!gather) {
                av = *(const float4*)(A + row * D_ + k);
            } else {
                int b = row >> 2, l = row & 3, h = k >> 7, hd = k & 127;
                av = *(const float4*)(A + (((b << 4) + h) * 4 + l) * HD_ + hd);
            }
            float4 bv = *(const float4*)(W + (n0 + row) * D_ + k);
            As[c4+0][row] = av.x; As[c4+1][row] = av.y;
            As[c4+2][row] = av.z; As[c4+3][row] = av.w;
            Bs[c4+0][row] = bv.x; Bs[c4+1][row] = bv.y;
            Bs[c4+2][row] = bv.z; Bs[c4+3][row] = bv.w;
        }
        __syncthreads();
        #pragma unroll
        for (int kk = 0; kk < 32; kk++) {
            float a[4], b[4];
            #pragma unroll
            for (int i = 0; i < 4; i++) a[i] = As[kk][ty*4 + i];
            #pragma unroll
            for (int j = 0; j < 4; j++) b[j] = Bs[kk][tx*4 + j];
            #pragma unroll
            for (int i = 0; i < 4; i++)
                #pragma unroll
                for (int j = 0; j < 4; j++)
                    acc[i][j] += a[i] * b[j];
        }
        __syncthreads();
    }

    #pragma unroll
    for (int i = 0; i < 4; i++)
        #pragma unroll
        for (int j = 0; j < 4; j++)
            atomicAdd(&C[(ty*4 + i) * D_ + n0 + tx*4 + j], acc[i][j]);
}

// ---------------------------------------------------------------------------
// rope + scatter: q -> g_q (roped), k -> keys tail (roped), v -> values tail
// ---------------------------------------------------------------------------
__global__ void rope_scatter(float* __restrict__ keys, float* __restrict__ values) {
    int mat = blockIdx.y;                       // 0=q, 1=k, 2=v
    int p = blockIdx.x * 256 + threadIdx.x;     // pair id, 0..65535
    int m  = p >> 10;                            // row 0..63
    int n0 = (p & 1023) * 2;                     // even column
    int b = m >> 2, l = m & 3;
    int h = n0 >> 7, hd = n0 & 127;
    const float* src = g_qkv + mat * M_ * D_ + m * D_ + n0;
    float x1 = src[0], x2 = src[1];
    int bh = (b << 4) + h;
    if (mat == 2) {
        float* dst = values + (bh * KVT + KV_ + l) * HD_ + hd;
        dst[0] = x1; dst[1] = x2;
    } else {
        int i = hd >> 1;
        float c = g_rc[l][i], s = g_rs[l][i];
        float r1 = x1 * c - x2 * s;
        float r2 = x1 * s + x2 * c;
        if (mat == 0) {
            float* dst = g_q + (bh * 4 + l) * HD_ + hd;
            dst[0] = r1; dst[1] = r2;
        } else {
            float* dst = keys + (bh * KVT + KV_ + l) * HD_ + hd;
            dst[0] = r1; dst[1] = r2;
        }
    }
}

// ---------------------------------------------------------------------------
// Fused K-cache copy + scores: warp per kv row, float4 per lane.
// ---------------------------------------------------------------------------
__global__ void kcopy_scores(const float* __restrict__ kc, const float* __restrict__ mask,
                             float* __restrict__ keys) {
    int bh = blockIdx.x;
    int start = blockIdx.y * CH;
    int end = min(start + CH, KVT);
    int len = end - start;
    int tid = threadIdx.x, w = tid >> 5, lane = tid & 31;
    __shared__ float ssc[4][CH];

    const float* qb = g_q + bh * 4 * HD_ + lane * 4;
    float4 q0 = *(const float4*)(qb + 0 * HD_);
    float4 q1 = *(const float4*)(qb + 1 * HD_);
    float4 q2 = *(const float4*)(qb + 2 * HD_);
    float4 q3 = *(const float4*)(qb + 3 * HD_);

    for (int r = start + w; r < end; r += 8) {
        float4 kv;
        int ko = (bh * KVT + r) * HD_ + lane * 4;
        if (r < KV_) {
            kv = *(const float4*)(kc + (bh * KV_ + r) * HD_ + lane * 4);
            *(float4*)(keys + ko) = kv;
        } else {
            kv = *(const float4*)(keys + ko);
        }
        float s0 = kv.x*q0.x + kv.y*q0.y + kv.z*q0.z + kv.w*q0.w;
        float s1 = kv.x*q1.x + kv.y*q1.y + kv.z*q1.z + kv.w*q1.w;
        float s2 = kv.x*q2.x + kv.y*q2.y + kv.z*q2.z + kv.w*q2.w;
        float s3 = kv.x*q3.x + kv.y*q3.y + kv.z*q3.z + kv.w*q3.w;
        #pragma unroll
        for (int off = 16; off; off >>= 1) {
            s0 += __shfl_xor_sync(0xFFFFFFFFu, s0, off);
            s1 += __shfl_xor_sync(0xFFFFFFFFu, s1, off);
            s2 += __shfl_xor_sync(0xFFFFFFFFu, s2, off);
            s3 += __shfl_xor_sync(0xFFFFFFFFu, s3, off);
        }
        if (lane == 0) {
            ssc[0][r - start] = s0; ssc[1][r - start] = s1;
            ssc[2][r - start] = s2; ssc[3][r - start] = s3;
        }
    }
    __syncthreads();
    const float scale = 0.08838834764831845f;   // 128^-0.5
    #pragma unroll
    for (int qi = 0; qi < 4; qi++)
        for (int i = tid; i < len; i += 256)
            g_scores[(bh * 4 + qi) * KVT + start + i] =
                ssc[qi][i] * scale + mask[qi * KVT + start + i];
}

// ---------------------------------------------------------------------------
// Softmax over 4100 per row, register-resident
// ---------------------------------------------------------------------------
__global__ void softmax_k() {
    int row = blockIdx.x;                  // bh*4+qi, 0..1023
    float* s = g_scores + row * KVT;
    int tid = threadIdx.x, lane = tid & 31, w = tid >> 5;
    __shared__ float red[8];

    float v[17];
    float mx = -3.0e38f;
    #pragma unroll
    for (int i = 0; i < 17; i++) {
        int idx = tid + i * 256;
        v[i] = (idx < KVT) ? s[idx] : -3.0e38f;
        mx = fmaxf(mx, v[i]);
    }
    #pragma unroll
    for (int off = 16; off; off >>= 1) mx = fmaxf(mx, __shfl_xor_sync(0xFFFFFFFFu, mx, off));
    if (lane == 0) red[w] = mx;
    __syncthreads();
    float bm = red[0];
    #pragma unroll
    for (int j = 1; j < 8; j++) bm = fmaxf(bm, red[j]);

    float sum = 0.f;
    #pragma unroll
    for (int i = 0; i < 17; i++) { v[i] = expf(v[i] - bm); sum += v[i]; }
    #pragma unroll
    for (int off = 16; off; off >>= 1) sum += __shfl_xor_sync(0xFFFFFFFFu, sum, off);
    __syncthreads();
    if (lane == 0) red[w] = sum;
    __syncthreads();
    float tot = 0.f;
    #pragma unroll
    for (int j = 0; j < 8; j++) tot += red[j];
    float inv = 1.0f / tot;
    #pragma unroll
    for (int i = 0; i < 17; i++) {
        int idx = tid + i * 256;
        if (idx < KVT) s[idx] = v[i] * inv;
    }
}

// ---------------------------------------------------------------------------
// Fused V-cache copy + attn @ V accumulation
// ---------------------------------------------------------------------------
__global__ void vcopy_out(const float* __restrict__ vc, float* __restrict__ values) {
    int bh = blockIdx.x;
    int start = blockIdx.y * CH;
    int end = min(start + CH, KVT);
    int len = end - start;
    int tid = threadIdx.x, w = tid >> 5, lane = tid & 31;
    __shared__ __align__(16) float sp[CH * 4];   // [row_local][qi]

    #pragma unroll
    for (int qi = 0; qi < 4; qi++)
        for (int i = tid; i < len; i += 256)
            sp[i * 4 + qi] = g_scores[(bh * 4 + qi) * KVT + start + i];
    __syncthreads();

    float a0[4] = {}, a1[4] = {}, a2[4] = {}, a3[4] = {};
    for (int r = start + w; r < end; r += 8) {
        float4 v;
        int vo = (bh * KVT + r) * HD_ + lane * 4;
        if (r < KV_) {
            v = *(const float4*)(vc + (bh * KV_ + r) * HD_ + lane * 4);
            *(float4*)(values + vo) = v;
        } else {
            v = *(const float4*)(values + vo);
        }
        float4 p = *(const float4*)(sp + (r - start) * 4);
        a0[0] += p.x*v.x; a0[1] += p.x*v.y; a0[2] += p.x*v.z; a0[3] += p.x*v.w;
        a1[0] += p.y*v.x; a1[1] += p.y*v.y; a1[2] += p.y*v.z; a1[3] += p.y*v.w;
        a2[0] += p.z*v.x; a2[1] += p.z*v.y; a2[2] += p.z*v.z; a2[3] += p.z*v.w;
        a3[0] += p.w*v.x; a3[1] += p.w*v.y; a3[2] += p.w*v.z; a3[3] += p.w*v.w;
    }
    float* ao = g_attnout + bh * 4 * HD_ + lane * 4;
    #pragma unroll
    for (int e = 0; e < 4; e++) {
        atomicAdd(&ao[0 * HD_ + e], a0[e]);
        atomicAdd(&ao[1 * HD_ + e], a1[e]);
        atomicAdd(&ao[2 * HD_ + e], a2[e]);
        atomicAdd(&ao[3 * HD_ + e], a3[e]);
    }
}

// ---------------------------------------------------------------------------
extern "C" void kernel_launch(void* const* d_in, const int* in_sizes, int n_in,
                              void* d_out, int out_size) {
    const float* x    = (const float*)d_in[0];
    const float* mask = (const float*)d_in[1];
    const float* kc   = (const float*)d_in[2];
    const float* vc   = (const float*)d_in[3];
    const float* qw   = (const float*)d_in[4];
    const float* kw   = (const float*)d_in[5];
    const float* vw   = (const float*)d_in[6];
    const float* ow   = (const float*)d_in[7];

    float* out    = (float*)d_out;
    float* keys   = out + OUT_ELEMS;
    float* values = keys + KEYS_ELEMS;

    init_kernel<<<1536, 256>>>(out);

    gemm64<<<dim3(32, 2), 256>>>(x, qw, nullptr, 0);
    gemm64<<<dim3(32, 2), 256>>>(x, kw, nullptr, 1);
    gemm64<<<dim3(32, 2), 256>>>(x, vw, nullptr, 2);

    rope_scatter<<<dim3(256, 3), 256>>>(keys, values);

    kcopy_scores<<<dim3(BH, NCH), 256>>>(kc, mask, keys);
    softmax_k<<<BH * L_, 256>>>();
    vcopy_out<<<dim3(BH, NCH), 256>>>(vc, values);

    gemm64<<<dim3(32, 4), 256>>>(nullptr, ow, out, 3);
}